// round 5
// baseline (speedup 1.0000x reference)
#include <cuda_runtime.h>
#include <cuda_bf16.h>
#include <cstdint>

#define Bb 2
#define Ss 2048
#define Dd 512
#define Hh 8
#define HDIM 64
#define SCALE 0.125f

// f32 scratch only for final; everything else lives as bf16 hi/lo planes.
__device__ uint16_t g_gene_h[Bb*Ss*Dd], g_gene_l[Bb*Ss*Dd];
__device__ uint16_t g_expr_h[Bb*Ss*Dd], g_expr_l[Bb*Ss*Dd];
__device__ uint16_t g_fus_h[Bb*Ss*Dd],  g_fus_l[Bb*Ss*Dd];
__device__ uint16_t g_q_h[Bb*Ss*Dd],    g_q_l[Bb*Ss*Dd];
__device__ uint16_t g_k_h[Bb*Ss*Dd],    g_k_l[Bb*Ss*Dd];
__device__ uint16_t g_v_h[Bb*Ss*Dd],    g_v_l[Bb*Ss*Dd];
__device__ uint16_t g_at_h[Bb*Ss*Dd],   g_at_l[Bb*Ss*Dd];
__device__ uint16_t g_wf_h[2*Dd*Dd],    g_wf_l[2*Dd*Dd];
__device__ uint16_t g_wq_h[Dd*Dd], g_wq_l[Dd*Dd];
__device__ uint16_t g_wk_h[Dd*Dd], g_wk_l[Dd*Dd];
__device__ uint16_t g_wv_h[Dd*Dd], g_wv_l[Dd*Dd];
__device__ uint16_t g_wo_h[Dd*Dd], g_wo_l[Dd*Dd];
__device__ uint32_t g_mbits[Bb*Ss*(Ss/32)];

// ---------------------------------------------------------------------------
__device__ __forceinline__ uint32_t smem_u32(const void* p) {
    return (uint32_t)__cvta_generic_to_shared(p);
}
__device__ __forceinline__ void split2(float x, float y, uint32_t &hi, uint32_t &lo) {
    __nv_bfloat162 h = __floats2bfloat162_rn(x, y);
    float2 hf = __bfloat1622float2(h);
    __nv_bfloat162 l = __floats2bfloat162_rn(x - hf.x, y - hf.y);
    hi = reinterpret_cast<uint32_t&>(h);
    lo = reinterpret_cast<uint32_t&>(l);
}
__device__ __forceinline__ void mma16816(float c[4], const uint32_t* a, const uint32_t* b) {
    asm volatile(
        "mma.sync.aligned.m16n8k16.row.col.f32.bf16.bf16.f32 "
        "{%0,%1,%2,%3}, {%4,%5,%6,%7}, {%8,%9}, {%0,%1,%2,%3};\n"
        : "+f"(c[0]), "+f"(c[1]), "+f"(c[2]), "+f"(c[3])
        : "r"(a[0]), "r"(a[1]), "r"(a[2]), "r"(a[3]), "r"(b[0]), "r"(b[1]));
}
__device__ __forceinline__ void ldsm_x4(uint32_t a[4], uint32_t addr) {
    asm volatile("ldmatrix.sync.aligned.m8n8.x4.shared.b16 {%0,%1,%2,%3}, [%4];"
        : "=r"(a[0]), "=r"(a[1]), "=r"(a[2]), "=r"(a[3]) : "r"(addr));
}
__device__ __forceinline__ void ldsm_x4_t(uint32_t a[4], uint32_t addr) {
    asm volatile("ldmatrix.sync.aligned.m8n8.x4.trans.shared.b16 {%0,%1,%2,%3}, [%4];"
        : "=r"(a[0]), "=r"(a[1]), "=r"(a[2]), "=r"(a[3]) : "r"(addr));
}
__device__ __forceinline__ void cpa16(uint32_t dst, const void* src) {
    asm volatile("cp.async.cg.shared.global [%0], [%1], 16;" :: "r"(dst), "l"(src));
}
__device__ __forceinline__ void cpa_commit() { asm volatile("cp.async.commit_group;"); }
__device__ __forceinline__ void cpa_wait0() { asm volatile("cp.async.wait_group 0;"); }

// ---------------------------------------------------------------------------
__global__ __launch_bounds__(256) void maskbits_kernel(const float* __restrict__ M,
                                                       uint32_t* __restrict__ bits) {
    int idx = blockIdx.x * 256 + threadIdx.x;
    float v = M[idx];
    uint32_t b = __ballot_sync(0xffffffffu, v != 0.f);
    if ((threadIdx.x & 31) == 0) bits[idx >> 5] = b;
}

__global__ __launch_bounds__(256) void split_kernel(const float* __restrict__ in,
                                                    uint16_t* __restrict__ hi,
                                                    uint16_t* __restrict__ lo) {
    int i = (blockIdx.x * 256 + threadIdx.x) * 4;
    float4 v = *(const float4*)(in + i);
    uint32_t h0, l0, h1, l1;
    split2(v.x, v.y, h0, l0);
    split2(v.z, v.w, h1, l1);
    *(uint2*)(hi + i) = make_uint2(h0, h1);
    *(uint2*)(lo + i) = make_uint2(l0, l1);
}

// ---------------------------------------------------------------------------
// bf16x3 GEMM from pre-split planes. C = A[4096,K] @ W[K,512] + bias, xscale.
// Output: f32 (Cf) or hi/lo planes (Ch/Cl). BM=128 BN=64 BK=32, 2-stage cp.async.
// ---------------------------------------------------------------------------
#define GA_STR 40
#define GB_STR 72
#define G_STAGE 14848   // elems: 2*128*40 + 2*32*72

__global__ __launch_bounds__(256) void gemm_bf3_kernel(
    const uint16_t* __restrict__ A1h, const uint16_t* __restrict__ A1l,
    const uint16_t* __restrict__ A2h, const uint16_t* __restrict__ A2l,
    const uint16_t* __restrict__ Wh,  const uint16_t* __restrict__ Wl,
    const float* __restrict__ bias, float* __restrict__ Cf,
    uint16_t* __restrict__ Ch, uint16_t* __restrict__ Cl,
    int K, float xscale)
{
    extern __shared__ uint16_t sm[];
    const int tid  = threadIdx.x;
    const int lane = tid & 31, wid = tid >> 5;
    const int grp  = lane >> 2, tig = lane & 3;
    const int wm = (wid & 3) * 32, wn = (wid >> 2) * 32;
    const int rowBase = blockIdx.y * 128, colBase = blockIdx.x * 64;

    const int arow = ((lane >> 3) & 1) * 8 + (lane & 7);
    const int acol = (lane >> 4) * 8;
    const int brow = ((lane >> 3) & 1) * 8 + (lane & 7);
    const int bcol = (lane >> 4) * 8;

    // per-thread load coords
    const int ar0 = tid >> 2, ac0 = (tid & 3) * 8;          // A chunk 0 (of 2: +64 rows)
    const int wr0 = tid >> 3, wc0 = (tid & 7) * 8;          // W chunk

    float acc[2][4][4];
    #pragma unroll
    for (int mt = 0; mt < 2; mt++)
        #pragma unroll
        for (int nt = 0; nt < 4; nt++)
            #pragma unroll
            for (int j = 0; j < 4; j++) acc[mt][nt][j] = 0.f;

    const int NIT = K / 32;
    auto load_tile = [&](int it, int s) {
        int k0 = it * 32;
        const uint16_t* Aph = (k0 < Dd) ? A1h : A2h;
        const uint16_t* Apl = (k0 < Dd) ? A1l : A2l;
        int ka = k0 & (Dd - 1);
        uint32_t base = smem_u32(sm) + s * G_STAGE * 2;
        #pragma unroll
        for (int i = 0; i < 2; i++) {
            int r = ar0 + i * 64;
            const size_t g = (size_t)(rowBase + r) * Dd + ka + ac0;
            cpa16(base + (r * GA_STR + ac0) * 2,            Aph + g);
            cpa16(base + (5120 + r * GA_STR + ac0) * 2,     Apl + g);
        }
        const size_t gw = (size_t)(k0 + wr0) * Dd + colBase + wc0;
        cpa16(base + (10240 + wr0 * GB_STR + wc0) * 2, Wh + gw);
        cpa16(base + (12544 + wr0 * GB_STR + wc0) * 2, Wl + gw);
    };

    load_tile(0, 0);
    cpa_commit();

    for (int it = 0; it < NIT; it++) {
        cpa_wait0();
        __syncthreads();
        if (it + 1 < NIT) { load_tile(it + 1, (it + 1) & 1); cpa_commit(); }

        const uint16_t* Ah = sm + (it & 1) * G_STAGE;
        const uint16_t* Al = Ah + 5120;
        const uint16_t* Bh = Ah + 10240;
        const uint16_t* Bl = Ah + 12544;

        #pragma unroll
        for (int kk = 0; kk < 2; kk++) {
            uint32_t ah[2][4], al[2][4];
            #pragma unroll
            for (int mt = 0; mt < 2; mt++) {
                int off = (wm + mt * 16 + arow) * GA_STR + kk * 16 + acol;
                ldsm_x4(ah[mt], smem_u32(&Ah[off]));
                ldsm_x4(al[mt], smem_u32(&Al[off]));
            }
            #pragma unroll
            for (int nt2 = 0; nt2 < 2; nt2++) {
                uint32_t th[4], tl[4];
                int off = (kk * 16 + brow) * GB_STR + wn + nt2 * 16 + bcol;
                ldsm_x4_t(th, smem_u32(&Bh[off]));
                ldsm_x4_t(tl, smem_u32(&Bl[off]));
                #pragma unroll
                for (int mt = 0; mt < 2; mt++) {
                    mma16816(acc[mt][nt2*2],   ah[mt], th);
                    mma16816(acc[mt][nt2*2],   al[mt], th);
                    mma16816(acc[mt][nt2*2],   ah[mt], tl);
                    mma16816(acc[mt][nt2*2+1], ah[mt], th + 2);
                    mma16816(acc[mt][nt2*2+1], al[mt], th + 2);
                    mma16816(acc[mt][nt2*2+1], ah[mt], tl + 2);
                }
            }
        }
        __syncthreads();
    }

    #pragma unroll
    for (int mt = 0; mt < 2; mt++)
        #pragma unroll
        for (int nt = 0; nt < 4; nt++) {
            int row = rowBase + wm + mt * 16 + grp;
            int col = colBase + wn + nt * 8 + 2 * tig;
            float bx = bias[col], by = bias[col + 1];
            float v00 = (acc[mt][nt][0] + bx) * xscale;
            float v01 = (acc[mt][nt][1] + by) * xscale;
            float v10 = (acc[mt][nt][2] + bx) * xscale;
            float v11 = (acc[mt][nt][3] + by) * xscale;
            if (Cf) {
                *(float2*)(Cf + (size_t)row * Dd + col)       = make_float2(v00, v01);
                *(float2*)(Cf + (size_t)(row + 8) * Dd + col) = make_float2(v10, v11);
            } else {
                uint32_t h0, l0, h1, l1;
                split2(v00, v01, h0, l0);
                split2(v10, v11, h1, l1);
                *(uint32_t*)&Ch[(size_t)row * Dd + col]       = h0;
                *(uint32_t*)&Cl[(size_t)row * Dd + col]       = l0;
                *(uint32_t*)&Ch[(size_t)(row + 8) * Dd + col] = h1;
                *(uint32_t*)&Cl[(size_t)(row + 8) * Dd + col] = l1;
            }
        }
}

// ---------------------------------------------------------------------------
// Flash attention, bf16x3 HMMA, BQ=128 (8 warps x 16 rows), BK=64, 2-stage
// cp.async K/V. Q pre-scaled by SCALE (folded into Q GEMM). Masked p zeroed,
// so running l == reference's sum|A|. Writes attn hi/lo planes.
// ---------------------------------------------------------------------------
#define FSTR 72
#define F_STAGE 18432   // elems: 4 * 64*72

__global__ __launch_bounds__(256) void flash_bf3_kernel(
    const uint16_t* __restrict__ Qh, const uint16_t* __restrict__ Ql,
    const uint16_t* __restrict__ Kgh, const uint16_t* __restrict__ Kgl,
    const uint16_t* __restrict__ Vgh, const uint16_t* __restrict__ Vgl,
    const uint32_t* __restrict__ mbits,
    uint16_t* __restrict__ Oh, uint16_t* __restrict__ Ol)
{
    extern __shared__ uint16_t sm[];
    const int tid = threadIdx.x, lane = tid & 31, w = tid >> 5;
    const int grp = lane >> 2, tig = lane & 3;
    const int b = blockIdx.y >> 3, h = blockIdx.y & 7;
    const int q0 = blockIdx.x * 128;

    const int arow = ((lane >> 3) & 1) * 8 + (lane & 7);
    const int acol = (lane >> 4) * 8;
    const int brow = (lane >> 4) * 8 + (lane & 7);
    const int bcol = ((lane >> 3) & 1) * 8;

    // ---- stage Q planes (128 x 64) into smem, pull A-frags ----
    {
        uint32_t base = smem_u32(sm);
        #pragma unroll
        for (int i = 0; i < 4; i++) {
            int chunk = tid + i * 256;
            int r = chunk >> 3, c = (chunk & 7) * 8;
            const size_t g = (size_t)(b * Ss + q0 + r) * Dd + h * HDIM + c;
            cpa16(base + (r * FSTR + c) * 2,          Qh + g);
            cpa16(base + (9216 + r * FSTR + c) * 2,   Ql + g);
        }
        cpa_commit();
        cpa_wait0();
        __syncthreads();
    }
    uint32_t qh[4][4], ql[4][4];
    #pragma unroll
    for (int c = 0; c < 4; c++) {
        int off = (w * 16 + arow) * FSTR + c * 16 + acol;
        ldsm_x4(qh[c], smem_u32(&sm[off]));
        ldsm_x4(ql[c], smem_u32(&sm[9216 + off]));
    }
    __syncthreads();

    float oacc[8][4];
    #pragma unroll
    for (int n = 0; n < 8; n++)
        #pragma unroll
        for (int j = 0; j < 4; j++) oacc[n][j] = 0.f;
    float mrun[2] = {-3.0e38f, -3.0e38f}, lrun[2] = {0.f, 0.f};

    auto load_tile = [&](int it, int s) {
        int k0 = it * 64;
        uint32_t base = smem_u32(sm) + s * F_STAGE * 2;
        #pragma unroll
        for (int i = 0; i < 2; i++) {
            int chunk = tid + i * 256;
            int r = chunk >> 3, c = (chunk & 7) * 8;
            const size_t g = (size_t)(b * Ss + k0 + r) * Dd + h * HDIM + c;
            uint32_t d = (r * FSTR + c) * 2;
            cpa16(base + d,                 Kgh + g);
            cpa16(base + 4608 * 2 + d,      Kgl + g);
            cpa16(base + 9216 * 2 + d,      Vgh + g);
            cpa16(base + 13824 * 2 + d,     Vgl + g);
        }
    };

    load_tile(0, 0);
    cpa_commit();

    const int NT = Ss / 64;
    for (int it = 0; it < NT; it++) {
        cpa_wait0();
        __syncthreads();
        if (it + 1 < NT) { load_tile(it + 1, (it + 1) & 1); cpa_commit(); }

        const uint16_t* Kh = sm + (it & 1) * F_STAGE;
        const uint16_t* Kl = Kh + 4608;
        const uint16_t* Vh = Kh + 9216;
        const uint16_t* Vl = Kh + 13824;
        const int k0 = it * 64;

        // S = Qs @ K^T
        float sacc[8][4];
        #pragma unroll
        for (int n = 0; n < 8; n++)
            #pragma unroll
            for (int j = 0; j < 4; j++) sacc[n][j] = 0.f;
        #pragma unroll
        for (int g = 0; g < 4; g++)
            #pragma unroll
            for (int c = 0; c < 4; c++) {
                uint32_t kf[4], kfl[4];
                int off = (g * 16 + brow) * FSTR + c * 16 + bcol;
                ldsm_x4(kf,  smem_u32(&Kh[off]));
                ldsm_x4(kfl, smem_u32(&Kl[off]));
                mma16816(sacc[2*g],   qh[c], kf);
                mma16816(sacc[2*g],   ql[c], kf);
                mma16816(sacc[2*g],   qh[c], kfl);
                mma16816(sacc[2*g+1], qh[c], kf + 2);
                mma16816(sacc[2*g+1], ql[c], kf + 2);
                mma16816(sacc[2*g+1], qh[c], kfl + 2);
            }

        // ---- masked online softmax ----
        #pragma unroll
        for (int r = 0; r < 2; r++) {
            int qrow = q0 + w * 16 + grp + r * 8;
            size_t mb = ((size_t)(b * Ss) + qrow) * (Ss / 32) + (k0 >> 5);
            uint32_t bw0 = mbits[mb], bw1 = mbits[mb + 1];
            float tm = -3.0e38f;
            #pragma unroll
            for (int n = 0; n < 8; n++)
                #pragma unroll
                for (int e = 0; e < 2; e++) {
                    int col = n * 8 + 2 * tig + e;
                    uint32_t on = ((n < 4 ? bw0 : bw1) >> (col & 31)) & 1u;
                    float sv = on ? sacc[n][r*2+e] : -1.0e9f;
                    sacc[n][r*2+e] = sv;
                    tm = fmaxf(tm, sv);
                }
            tm = fmaxf(tm, __shfl_xor_sync(0xffffffffu, tm, 1));
            tm = fmaxf(tm, __shfl_xor_sync(0xffffffffu, tm, 2));
            float mn = fmaxf(mrun[r], tm);
            float co = __expf(mrun[r] - mn);
            float ps = 0.f;
            #pragma unroll
            for (int n = 0; n < 8; n++)
                #pragma unroll
                for (int e = 0; e < 2; e++) {
                    float sv = sacc[n][r*2+e];
                    float p = (sv == -1.0e9f) ? 0.f : __expf(sv - mn);
                    sacc[n][r*2+e] = p;
                    ps += p;
                }
            ps += __shfl_xor_sync(0xffffffffu, ps, 1);
            ps += __shfl_xor_sync(0xffffffffu, ps, 2);
            mrun[r] = mn;
            lrun[r] = lrun[r] * co + ps;
            #pragma unroll
            for (int n = 0; n < 8; n++) {
                oacc[n][r*2]   *= co;
                oacc[n][r*2+1] *= co;
            }
        }

        // ---- O += P @ V ----
        #pragma unroll
        for (int kc = 0; kc < 4; kc++) {
            uint32_t ah[4], al[4];
            split2(sacc[2*kc][0],   sacc[2*kc][1],   ah[0], al[0]);
            split2(sacc[2*kc][2],   sacc[2*kc][3],   ah[1], al[1]);
            split2(sacc[2*kc+1][0], sacc[2*kc+1][1], ah[2], al[2]);
            split2(sacc[2*kc+1][2], sacc[2*kc+1][3], ah[3], al[3]);
            #pragma unroll
            for (int c = 0; c < 4; c++) {
                uint32_t vf[4], vfl[4];
                int off = (kc * 16 + arow) * FSTR + c * 16 + acol;
                ldsm_x4_t(vf,  smem_u32(&Vh[off]));
                ldsm_x4_t(vfl, smem_u32(&Vl[off]));
                mma16816(oacc[2*c],   ah, vf);
                mma16816(oacc[2*c],   al, vf);
                mma16816(oacc[2*c],   ah, vfl);
                mma16816(oacc[2*c+1], ah, vf + 2);
                mma16816(oacc[2*c+1], al, vf + 2);
                mma16816(oacc[2*c+1], ah, vfl + 2);
            }
        }
        __syncthreads();
    }

    // ---- epilogue: divide by l, write hi/lo planes ----
    float inv0 = (lrun[0] > 0.f) ? 1.f / lrun[0] : 0.f;
    float inv1 = (lrun[1] > 0.f) ? 1.f / lrun[1] : 0.f;
    int row0 = b * Ss + q0 + w * 16 + grp;
    #pragma unroll
    for (int n = 0; n < 8; n++) {
        int col = h * HDIM + n * 8 + 2 * tig;
        uint32_t h0, l0, h1, l1;
        split2(oacc[n][0] * inv0, oacc[n][1] * inv0, h0, l0);
        split2(oacc[n][2] * inv1, oacc[n][3] * inv1, h1, l1);
        *(uint32_t*)&Oh[(size_t)row0 * Dd + col]       = h0;
        *(uint32_t*)&Ol[(size_t)row0 * Dd + col]       = l0;
        *(uint32_t*)&Oh[(size_t)(row0 + 8) * Dd + col] = h1;
        *(uint32_t*)&Ol[(size_t)(row0 + 8) * Dd + col] = l1;
    }
}

// ---------------------------------------------------------------------------
extern "C" void kernel_launch(void* const* d_in, const int* in_sizes, int n_in,
                              void* d_out, int out_size)
{
    const float* gene = (const float*)d_in[0];
    const float* expr = (const float*)d_in[1];
    const float* Mm   = (const float*)d_in[2];
    const float* Wf   = (const float*)d_in[3];
    const float* bf   = (const float*)d_in[4];
    const float* Wq   = (const float*)d_in[5];
    const float* bq   = (const float*)d_in[6];
    const float* Wk   = (const float*)d_in[7];
    const float* bk   = (const float*)d_in[8];
    const float* Wv   = (const float*)d_in[9];
    const float* bv   = (const float*)d_in[10];
    const float* Wo   = (const float*)d_in[11];
    const float* bo   = (const float*)d_in[12];
    float* out = (float*)d_out;

    uint16_t *geneh, *genel, *exprh, *exprl, *fush, *fusl;
    uint16_t *qh, *ql, *kh, *kl, *vh, *vl, *ath, *atl;
    uint16_t *wfh, *wfl, *wqh, *wql, *wkh, *wkl, *wvh, *wvl, *woh, *wol;
    uint32_t* mbits;
    cudaGetSymbolAddress((void**)&geneh, g_gene_h); cudaGetSymbolAddress((void**)&genel, g_gene_l);
    cudaGetSymbolAddress((void**)&exprh, g_expr_h); cudaGetSymbolAddress((void**)&exprl, g_expr_l);
    cudaGetSymbolAddress((void**)&fush,  g_fus_h);  cudaGetSymbolAddress((void**)&fusl,  g_fus_l);
    cudaGetSymbolAddress((void**)&qh,    g_q_h);    cudaGetSymbolAddress((void**)&ql,    g_q_l);
    cudaGetSymbolAddress((void**)&kh,    g_k_h);    cudaGetSymbolAddress((void**)&kl,    g_k_l);
    cudaGetSymbolAddress((void**)&vh,    g_v_h);    cudaGetSymbolAddress((void**)&vl,    g_v_l);
    cudaGetSymbolAddress((void**)&ath,   g_at_h);   cudaGetSymbolAddress((void**)&atl,   g_at_l);
    cudaGetSymbolAddress((void**)&wfh,   g_wf_h);   cudaGetSymbolAddress((void**)&wfl,   g_wf_l);
    cudaGetSymbolAddress((void**)&wqh,   g_wq_h);   cudaGetSymbolAddress((void**)&wql,   g_wq_l);
    cudaGetSymbolAddress((void**)&wkh,   g_wk_h);   cudaGetSymbolAddress((void**)&wkl,   g_wk_l);
    cudaGetSymbolAddress((void**)&wvh,   g_wv_h);   cudaGetSymbolAddress((void**)&wvl,   g_wv_l);
    cudaGetSymbolAddress((void**)&woh,   g_wo_h);   cudaGetSymbolAddress((void**)&wol,   g_wo_l);
    cudaGetSymbolAddress((void**)&mbits, g_mbits);

    cudaFuncSetAttribute(gemm_bf3_kernel,  cudaFuncAttributeMaxDynamicSharedMemorySize, 2 * G_STAGE * 2);
    cudaFuncSetAttribute(flash_bf3_kernel, cudaFuncAttributeMaxDynamicSharedMemorySize, 2 * F_STAGE * 2);

    const int NE = Bb * Ss * Dd;                 // 2M elems
    maskbits_kernel<<<(Bb * Ss * Ss) / 256, 256>>>(Mm, mbits);
    split_kernel<<<NE / 1024, 256>>>(gene, geneh, genel);
    split_kernel<<<NE / 1024, 256>>>(expr, exprh, exprl);
    split_kernel<<<(2 * Dd * Dd) / 1024, 256>>>(Wf, wfh, wfl);
    split_kernel<<<(Dd * Dd) / 1024, 256>>>(Wq, wqh, wql);
    split_kernel<<<(Dd * Dd) / 1024, 256>>>(Wk, wkh, wkl);
    split_kernel<<<(Dd * Dd) / 1024, 256>>>(Wv, wvh, wvl);
    split_kernel<<<(Dd * Dd) / 1024, 256>>>(Wo, woh, wol);

    dim3 gridP(Dd / 64, (Bb * Ss) / 128);        // (8, 32)
    const int gsm = 2 * G_STAGE * 2;
    // fused = [gene; expr] @ Wf + bf   (K=1024, A switches at k=512)
    gemm_bf3_kernel<<<gridP, 256, gsm>>>(geneh, genel, exprh, exprl, wfh, wfl, bf,
                                         nullptr, fush, fusl, 2 * Dd, 1.f);
    gemm_bf3_kernel<<<gridP, 256, gsm>>>(fush, fusl, fush, fusl, wqh, wql, bq,
                                         nullptr, qh, ql, Dd, SCALE);   // scale folded into Q
    gemm_bf3_kernel<<<gridP, 256, gsm>>>(fush, fusl, fush, fusl, wkh, wkl, bk,
                                         nullptr, kh, kl, Dd, 1.f);
    gemm_bf3_kernel<<<gridP, 256, gsm>>>(exprh, exprl, exprh, exprl, wvh, wvl, bv,
                                         nullptr, vh, vl, Dd, 1.f);

    dim3 gridA(Ss / 128, Bb * Hh);               // (16, 16)
    flash_bf3_kernel<<<gridA, 256, 2 * F_STAGE * 2>>>(qh, ql, kh, kl, vh, vl, mbits, ath, atl);

    gemm_bf3_kernel<<<gridP, 256, gsm>>>(ath, atl, ath, atl, woh, wol, bo,
                                         out, nullptr, nullptr, Dd, 1.f);
}